// round 15
// baseline (speedup 1.0000x reference)
#include <cuda_runtime.h>
#include <cuda_bf16.h>
#include <cuda_fp16.h>
#include <math.h>
#include <stdint.h>

#define BS_  2
#define SEQ  2048
#define EMB  1024
#define NH   16
#define HD   64
#define MROWS (BS_*SEQ)   // 4096
#define ANELEM ((size_t)MROWS*EMB)
#define WNELEM ((size_t)EMB*EMB)

// ------------------------- scratch (__device__ globals) ---------------------
// x: z=0,1 bf16 hi/lo (query,key); z=2 fp16 single (value, hi slot only)
__device__ __nv_bfloat16 g_xhi[3*ANELEM];
__device__ __nv_bfloat16 g_xlo[3*ANELEM];
// w: 0,1 bf16 hi/lo (Wq,Wk); 2,3 fp16 hi/lo (Wv,Wo)
__device__ __nv_bfloat16 g_whi[4*WNELEM];
__device__ __nv_bfloat16 g_wlo[4*WNELEM];
__device__ __nv_bfloat16 g_qhi[ANELEM];     // roped+scaled Q (bf16 hi/lo)
__device__ __nv_bfloat16 g_qlo[ANELEM];
__device__ __nv_bfloat16 g_khi[ANELEM];     // roped K (bf16 hi/lo)
__device__ __nv_bfloat16 g_klo[ANELEM];
__device__ __nv_bfloat16 g_vhi[ANELEM];     // V (fp16 hi/lo, raw bits)
__device__ __nv_bfloat16 g_vlo[ANELEM];
__device__ __nv_bfloat16 g_ahi[ANELEM];     // attention out (fp16 single, raw bits)
__device__ float g_cs[SEQ*32];
__device__ float g_sn[SEQ*32];

// ------------------------- helpers ------------------------------------------
__device__ __forceinline__ uint32_t smem_u32(const void* p) {
    uint32_t a;
    asm("{ .reg .u64 t; cvta.to.shared.u64 t, %1; cvt.u32.u64 %0, t; }"
        : "=r"(a) : "l"(p));
    return a;
}
#define CP16(dst, src) \
    asm volatile("cp.async.cg.shared.global [%0], [%1], 16;" :: "r"(dst), "l"(src) : "memory")
#define CP_COMMIT() asm volatile("cp.async.commit_group;" ::: "memory")
#define CP_WAIT(n)  asm volatile("cp.async.wait_group %0;" :: "n"(n) : "memory")

__device__ __forceinline__ void ldsm4(uint32_t* r, uint32_t addr) {
    asm volatile("ldmatrix.sync.aligned.m8n8.x4.shared.b16 {%0,%1,%2,%3}, [%4];"
                 : "=r"(r[0]), "=r"(r[1]), "=r"(r[2]), "=r"(r[3]) : "r"(addr));
}
__device__ __forceinline__ void ldsm4t(uint32_t* r, uint32_t addr) {
    asm volatile("ldmatrix.sync.aligned.m8n8.x4.trans.shared.b16 {%0,%1,%2,%3}, [%4];"
                 : "=r"(r[0]), "=r"(r[1]), "=r"(r[2]), "=r"(r[3]) : "r"(addr));
}
__device__ __forceinline__ void mma16816(float* c, const uint32_t* a,
                                         uint32_t b0, uint32_t b1) {
    asm volatile("mma.sync.aligned.m16n8k16.row.col.f32.bf16.bf16.f32 "
                 "{%0,%1,%2,%3}, {%4,%5,%6,%7}, {%8,%9}, {%0,%1,%2,%3};"
                 : "+f"(c[0]), "+f"(c[1]), "+f"(c[2]), "+f"(c[3])
                 : "r"(a[0]), "r"(a[1]), "r"(a[2]), "r"(a[3]), "r"(b0), "r"(b1));
}
__device__ __forceinline__ void mma16816h(float* c, const uint32_t* a,
                                          uint32_t b0, uint32_t b1) {
    asm volatile("mma.sync.aligned.m16n8k16.row.col.f32.f16.f16.f32 "
                 "{%0,%1,%2,%3}, {%4,%5,%6,%7}, {%8,%9}, {%0,%1,%2,%3};"
                 : "+f"(c[0]), "+f"(c[1]), "+f"(c[2]), "+f"(c[3])
                 : "r"(a[0]), "r"(a[1]), "r"(a[2]), "r"(a[3]), "r"(b0), "r"(b1));
}
__device__ __forceinline__ uint32_t swz(uint32_t off) { return off ^ ((off >> 3) & 0x70); }
__device__ __forceinline__ uint32_t pack_h(float lo, float hi) {
    uint32_t r;
    asm("cvt.rn.f16x2.f32 %0, %1, %2;" : "=r"(r) : "f"(hi), "f"(lo));
    return r;
}
__device__ __forceinline__ float ex2(float x) {
    float r;
    asm("ex2.approx.ftz.f32 %0, %1;" : "=f"(r) : "f"(x));
    return r;
}

// ------------------------- fused splits + rope table -------------------------
// z=0,1: bf16 hi/lo (q,k). z=2: fp16 single (v). z=3,4: bf16 hi/lo (Wq,Wk).
// z=5,6: fp16 hi/lo (Wv,Wo). z=7: rope table.
__global__ __launch_bounds__(256) void split_all(
    const float* __restrict__ q, const float* __restrict__ k,
    const float* __restrict__ v, const float* __restrict__ wq,
    const float* __restrict__ wk, const float* __restrict__ wv,
    const float* __restrict__ wo)
{
    const int z = blockIdx.z;
    if (z == 7) {
        int i = blockIdx.x * 256 + threadIdx.x;
        if (i < SEQ*32) {
            int s = i >> 5, d = i & 31;
            float inv = exp2f(-(float)d * (13.287712379549449f / 32.0f));
            float sn, cs;
            sincosf((float)s * inv, &sn, &cs);
            g_cs[i] = cs; g_sn[i] = sn;
        }
        return;
    }
    const float* src;
    uint16_t *hi, *lo;
    int n4, kind;   // kind: 0 bf16 hi/lo, 1 fp16 single, 2 fp16 hi/lo
    if (z < 3) {
        src = (z == 0) ? q : (z == 1) ? k : v;
        hi = (uint16_t*)(g_xhi + (size_t)z * ANELEM);
        lo = (uint16_t*)(g_xlo + (size_t)z * ANELEM);
        n4 = (int)(ANELEM / 4);
        kind = (z == 2) ? 1 : 0;
    } else {
        src = (z == 3) ? wq : (z == 4) ? wk : (z == 5) ? wv : wo;
        hi = (uint16_t*)(g_whi + (size_t)(z - 3) * WNELEM);
        lo = (uint16_t*)(g_wlo + (size_t)(z - 3) * WNELEM);
        n4 = (int)(WNELEM / 4);
        kind = (z >= 5) ? 2 : 0;
    }
    const int base = blockIdx.x * 2048 + threadIdx.x;
    #pragma unroll
    for (int it = 0; it < 8; it++) {
        const int i = base + it * 256;
        if (i >= n4) continue;
        float4 val = ((const float4*)src)[i];
        float vv[4] = {val.x, val.y, val.z, val.w};
        uint16_t h[4], l[4];
        if (kind == 0) {
            #pragma unroll
            for (int j = 0; j < 4; j++) {
                __nv_bfloat16 hb = __float2bfloat16(vv[j]);
                __nv_bfloat16 lb = __float2bfloat16(vv[j] - __bfloat162float(hb));
                h[j] = *(uint16_t*)&hb; l[j] = *(uint16_t*)&lb;
            }
            ((uint2*)hi)[i] = *(uint2*)h;
            ((uint2*)lo)[i] = *(uint2*)l;
        } else if (kind == 1) {
            #pragma unroll
            for (int j = 0; j < 4; j++)
                h[j] = __half_as_ushort(__float2half_rn(vv[j]));
            ((uint2*)hi)[i] = *(uint2*)h;
        } else {
            #pragma unroll
            for (int j = 0; j < 4; j++) {
                __half hh = __float2half_rn(vv[j]);
                __half ll = __float2half_rn(vv[j] - __half2float(hh));
                h[j] = __half_as_ushort(hh); l[j] = __half_as_ushort(ll);
            }
            ((uint2*)hi)[i] = *(uint2*)h;
            ((uint2*)lo)[i] = *(uint2*)l;
        }
    }
}

// ------------------------- shared GEMM pieces --------------------------------
// 128x64 CTA tile, Kc=64 (128B rows, SW128), 256 threads, warp grid 4M x 2N,
// warp tile 32x32. Single-barrier 2-stage cp.async.
#define GA_PART 16384                     // 128 rows x 128B
#define GB_PART 8192                      // 64 rows x 128B
#define NSTAGE 16

__device__ __forceinline__ void load_tileA(uint32_t sdst, const uint16_t* g,
                                           int row0, int kc0, int tid)
{
    const uint16_t* gp = g + (size_t)row0 * EMB + kc0;
    #pragma unroll
    for (int it = 0; it < 4; it++) {
        int lin = it * 256 + tid;
        int r = lin >> 3, cq = (lin & 7) << 3;
        CP16(sdst + swz((uint32_t)(r * 128 + cq * 2)), gp + (size_t)r * EMB + cq);
    }
}
__device__ __forceinline__ void load_tileB(uint32_t sdst, const uint16_t* g,
                                           int row0, int kc0, int tid)
{
    const uint16_t* gp = g + (size_t)row0 * EMB + kc0;
    #pragma unroll
    for (int it = 0; it < 2; it++) {
        int lin = it * 256 + tid;
        int r = lin >> 3, cq = (lin & 7) << 3;
        CP16(sdst + swz((uint32_t)(r * 128 + cq * 2)), gp + (size_t)r * EMB + cq);
    }
}

#define QSCL 0.18033688011112042f   // (1/8) * log2(e)

// ---- bf16 3-pass core: Q (emode 2 + scale) and K (emode 2) projections -----
#define GSM3_STAGE (2*GA_PART + 2*GB_PART)   // 49152
#define GSM3_TOTAL (2*GSM3_STAGE)            // 98304

__global__ __launch_bounds__(256, 2) void tc_gemm_qk(
    const float* __restrict__ bq, const float* __restrict__ bk)
{
    const int z = blockIdx.z;    // 0=Q, 1=K
    const uint16_t* Ahi = (const uint16_t*)(g_xhi + (size_t)z * ANELEM);
    const uint16_t* Alo = (const uint16_t*)(g_xlo + (size_t)z * ANELEM);
    const uint16_t* Bhi = (const uint16_t*)(g_whi + (size_t)z * WNELEM);
    const uint16_t* Blo = (const uint16_t*)(g_wlo + (size_t)z * WNELEM);
    const float* bias = (z == 0) ? bq : bk;
    __nv_bfloat16* Ch = (z == 0) ? g_qhi : g_khi;
    __nv_bfloat16* Cl = (z == 0) ? g_qlo : g_klo;
    const float oscale = (z == 0) ? QSCL : 1.0f;

    extern __shared__ char sm[];
    const uint32_t sbase = smem_u32(sm);
    const int tid  = threadIdx.x;
    const int wid  = tid >> 5, lane = tid & 31;
    const int wm   = wid >> 1, wn = wid & 1;
    const int bm   = blockIdx.y * 128, bn = blockIdx.x * 64;

    float acc[2][4][4];
    #pragma unroll
    for (int i = 0; i < 2; i++)
        #pragma unroll
        for (int j = 0; j < 4; j++)
            #pragma unroll
            for (int e = 0; e < 4; e++) acc[i][j][e] = 0.f;

    const int lrow = lane & 15;
    const int lchk = lane >> 4;
    uint32_t offA[2], offB[2];
    #pragma unroll
    for (int i = 0; i < 2; i++) offA[i] = (uint32_t)((wm*32 + i*16 + lrow) * 128);
    #pragma unroll
    for (int jg = 0; jg < 2; jg++) offB[jg] = (uint32_t)((wn*16 + jg*32 + lrow) * 128);

    {
        uint32_t buf = sbase;
        load_tileA(buf,                       Ahi, bm, 0, tid);
        load_tileA(buf + GA_PART,             Alo, bm, 0, tid);
        load_tileB(buf + 2*GA_PART,           Bhi, bn, 0, tid);
        load_tileB(buf + 2*GA_PART + GB_PART, Blo, bn, 0, tid);
        CP_COMMIT();
    }

    for (int s = 0; s < NSTAGE; s++) {
        const uint32_t cbuf = sbase + (uint32_t)(s & 1) * GSM3_STAGE;
        CP_WAIT(0);
        __syncthreads();
        if (s + 1 < NSTAGE) {
            uint32_t buf = sbase + (uint32_t)((s + 1) & 1) * GSM3_STAGE;
            int kc = (s + 1) * 64;
            load_tileA(buf,                       Ahi, bm, kc, tid);
            load_tileA(buf + GA_PART,             Alo, bm, kc, tid);
            load_tileB(buf + 2*GA_PART,           Bhi, bn, kc, tid);
            load_tileB(buf + 2*GA_PART + GB_PART, Blo, bn, kc, tid);
            CP_COMMIT();
        }

        #pragma unroll
        for (int kk = 0; kk < 4; kk++) {
            const uint32_t kb = (uint32_t)((kk*2 + lchk) * 16);
            uint32_t ah[2][4], al[2][4];
            #pragma unroll
            for (int i = 0; i < 2; i++) {
                ldsm4(ah[i], cbuf + swz(offA[i] + kb));
                ldsm4(al[i], cbuf + GA_PART + swz(offA[i] + kb));
            }
            #pragma unroll
            for (int jg = 0; jg < 2; jg++) {
                uint32_t bh[4], bl[4];
                ldsm4(bh, cbuf + 2*GA_PART + swz(offB[jg] + kb));
                ldsm4(bl, cbuf + 2*GA_PART + GB_PART + swz(offB[jg] + kb));
                #pragma unroll
                for (int i = 0; i < 2; i++) {
                    mma16816(acc[i][jg*2],   ah[i], bh[0], bh[2]);
                    mma16816(acc[i][jg*2+1], ah[i], bh[1], bh[3]);
                    mma16816(acc[i][jg*2],   ah[i], bl[0], bl[2]);
                    mma16816(acc[i][jg*2+1], ah[i], bl[1], bl[3]);
                    mma16816(acc[i][jg*2],   al[i], bh[0], bh[2]);
                    mma16816(acc[i][jg*2+1], al[i], bh[1], bh[3]);
                }
            }
        }
    }

    // rope epilogue (bf16 hi/lo scatter)
    const int grp = lane >> 2;
    const int cpo = (lane & 3) * 2;
    const int hh  = bn >> 6;
    #pragma unroll
    for (int i = 0; i < 2; i++) {
        #pragma unroll
        for (int half = 0; half < 2; half++) {
            const int row = bm + wm*32 + i*16 + grp + half*8;
            const int bb = row >> 11, ss = row & 2047;
            #pragma unroll
            for (int t = 0; t < 2; t++)
                #pragma unroll
                for (int e = 0; e < 2; e++) {
                    const int d  = wn*16 + t*8 + cpo + e;   // 0..31
                    const float x1 = acc[i][t][half*2+e]   + bias[bn + d];
                    const float x2 = acc[i][2+t][half*2+e] + bias[bn + d + 32];
                    const float cs = g_cs[ss*32 + d];
                    const float sn = g_sn[ss*32 + d];
                    const float y1 = (x1*cs - x2*sn) * oscale;
                    const float y2 = (x2*cs + x1*sn) * oscale;
                    const __nv_bfloat16 h1 = __float2bfloat16(y1);
                    const __nv_bfloat16 h2 = __float2bfloat16(y2);
                    const __nv_bfloat16 l1 = __float2bfloat16(y1 - __bfloat162float(h1));
                    const __nv_bfloat16 l2 = __float2bfloat16(y2 - __bfloat162float(h2));
                    const size_t base = (((size_t)bb*NH + hh)*SEQ + ss)*HD + d;
                    Ch[base]      = h1; Cl[base]      = l1;
                    Ch[base + 32] = h2; Cl[base + 32] = l2;
                }
        }
    }
}

// ---- fp16 2-pass core: A single fp16, B fp16 hi/lo --------------------------
// emode 1: fp32 row-major out. emode 3: fp16 hi/lo scatter [B,H,S,D].
#define GSMH_STAGE (GA_PART + 2*GB_PART)     // 32768
#define GSMH_TOTAL (2*GSMH_STAGE)            // 65536

__device__ __forceinline__ void gemm_core_h(
    const uint16_t* __restrict__ A,
    const uint16_t* __restrict__ Bhi, const uint16_t* __restrict__ Blo,
    const float* __restrict__ bias,
    uint16_t* __restrict__ Ch, uint16_t* __restrict__ Cl,
    float* __restrict__ Cf, int emode)
{
    extern __shared__ char sm[];
    const uint32_t sbase = smem_u32(sm);
    const int tid  = threadIdx.x;
    const int wid  = tid >> 5, lane = tid & 31;
    const int wm   = wid >> 1, wn = wid & 1;
    const int bm   = blockIdx.y * 128, bn = blockIdx.x * 64;

    float acc[2][4][4];
    #pragma unroll
    for (int i = 0; i < 2; i++)
        #pragma unroll
        for (int j = 0; j < 4; j++)
            #pragma unroll
            for (int e = 0; e < 4; e++) acc[i][j][e] = 0.f;

    const int lrow = lane & 15;
    const int lchk = lane >> 4;
    uint32_t offA[2], offB[2];
    #pragma unroll
    for (int i = 0; i < 2; i++) offA[i] = (uint32_t)((wm*32 + i*16 + lrow) * 128);
    #pragma unroll
    for (int jg = 0; jg < 2; jg++) offB[jg] = (uint32_t)((wn*16 + jg*32 + lrow) * 128);

    {
        uint32_t buf = sbase;
        load_tileA(buf,                     A,   bm, 0, tid);
        load_tileB(buf + GA_PART,           Bhi, bn, 0, tid);
        load_tileB(buf + GA_PART + GB_PART, Blo, bn, 0, tid);
        CP_COMMIT();
    }

    for (int s = 0; s < NSTAGE; s++) {
        const uint32_t cbuf = sbase + (uint32_t)(s & 1) * GSMH_STAGE;
        CP_WAIT(0);
        __syncthreads();
        if (s + 1 < NSTAGE) {
            uint32_t buf = sbase + (uint32_t)((s + 1) & 1) * GSMH_STAGE;
            int kc = (s + 1) * 64;
            load_tileA(buf,                     A,   bm, kc, tid);
            load_tileB(buf + GA_PART,           Bhi, bn, kc, tid);
            load_tileB(buf + GA_PART + GB_PART, Blo, bn, kc, tid);
            CP_COMMIT();
        }

        #pragma unroll
        for (int kk = 0; kk < 4; kk++) {
            const uint32_t kb = (uint32_t)((kk*2 + lchk) * 16);
            uint32_t a[2][4];
            #pragma unroll
            for (int i = 0; i < 2; i++)
                ldsm4(a[i], cbuf + swz(offA[i] + kb));
            #pragma unroll
            for (int jg = 0; jg < 2; jg++) {
                uint32_t bh[4], bl[4];
                ldsm4(bh, cbuf + GA_PART + swz(offB[jg] + kb));
                ldsm4(bl, cbuf + GA_PART + GB_PART + swz(offB[jg] + kb));
                #pragma unroll
                for (int i = 0; i < 2; i++) {
                    mma16816h(acc[i][jg*2],   a[i], bh[0], bh[2]);
                    mma16816h(acc[i][jg*2+1], a[i], bh[1], bh[3]);
                    mma16816h(acc[i][jg*2],   a[i], bl[0], bl[2]);
                    mma16816h(acc[i][jg*2+1], a[i], bl[1], bl[3]);
                }
            }
        }
    }

    const int grp = lane >> 2;
    const int cpo = (lane & 3) * 2;
    #pragma unroll
    for (int i = 0; i < 2; i++) {
        #pragma unroll
        for (int half = 0; half < 2; half++) {
            const int row = bm + wm*32 + i*16 + grp + half*8;
            const int bb = row >> 11, ss = row & 2047;
            if (emode == 1) {
                #pragma unroll
                for (int jg = 0; jg < 2; jg++)
                    #pragma unroll
                    for (int t = 0; t < 2; t++) {
                        const int col = bn + wn*16 + jg*32 + t*8 + cpo;
                        Cf[(size_t)row * EMB + col]     = acc[i][jg*2+t][half*2]   + bias[col];
                        Cf[(size_t)row * EMB + col + 1] = acc[i][jg*2+t][half*2+1] + bias[col+1];
                    }
            } else {
                const int hh = bn >> 6;
                #pragma unroll
                for (int jg = 0; jg < 2; jg++)
                    #pragma unroll
                    for (int t = 0; t < 2; t++)
                        #pragma unroll
                        for (int e = 0; e < 2; e++) {
                            const int d = wn*16 + jg*32 + t*8 + cpo + e;
                            const float v = acc[i][jg*2+t][half*2+e] + bias[bn + d];
                            const __half hv = __float2half_rn(v);
                            const __half lv = __float2half_rn(v - __half2float(hv));
                            const size_t base = (((size_t)bb*NH + hh)*SEQ + ss)*HD + d;
                            Ch[base] = __half_as_ushort(hv);
                            Cl[base] = __half_as_ushort(lv);
                        }
            }
        }
    }
}

__global__ __launch_bounds__(256, 2) void tc_gemm_v(const float* __restrict__ bv)
{
    gemm_core_h((const uint16_t*)(g_xhi + 2*ANELEM),
                (const uint16_t*)(g_whi + 2*WNELEM),
                (const uint16_t*)(g_wlo + 2*WNELEM),
                bv, (uint16_t*)g_vhi, (uint16_t*)g_vlo, nullptr, 3);
}
__global__ __launch_bounds__(256, 2) void tc_gemm_o(const float* __restrict__ bo,
                                                    float* __restrict__ out)
{
    gemm_core_h((const uint16_t*)g_ahi,
                (const uint16_t*)(g_whi + 3*WNELEM),
                (const uint16_t*)(g_wlo + 3*WNELEM),
                bo, nullptr, nullptr, out, 1);
}

// ------------------------- tensor-core flash attention -----------------------
// QK: bf16 3-pass (log2 domain, Q pre-scaled). PV: fp16 2-pass.
// Output: single fp16 into g_ahi.
#define ATT_TOTAL (32768 + 2*32768)

__device__ __forceinline__ void load_kv(uint32_t st,
    const __nv_bfloat16* kh, const __nv_bfloat16* kl,
    const __nv_bfloat16* vh, const __nv_bfloat16* vl, int t0, int tid)
{
    #pragma unroll
    for (int it = 0; it < 2; it++) {
        int lin = it * 256 + tid;
        int r = lin >> 3, c = (lin & 7) * 16;
        uint32_t so = swz((uint32_t)(r * 128 + c));
        size_t go = (size_t)(t0 + r) * 128 + c;
        CP16(st + so,          (const char*)kh + go);
        CP16(st + 8192 + so,   (const char*)kl + go);
        CP16(st + 16384 + so,  (const char*)vh + go);
        CP16(st + 24576 + so,  (const char*)vl + go);
    }
}

__global__ __launch_bounds__(256, 2) void attn_tc(
    const __nv_bfloat16* __restrict__ qhi, const __nv_bfloat16* __restrict__ qlo,
    const __nv_bfloat16* __restrict__ khi, const __nv_bfloat16* __restrict__ klo,
    const __nv_bfloat16* __restrict__ vhi, const __nv_bfloat16* __restrict__ vlo,
    uint16_t* __restrict__ oout)
{
    extern __shared__ char sm[];
    const uint32_t sb = smem_u32(sm);
    const int tid = threadIdx.x, wid = tid >> 5, lane = tid & 31;
    const int qt = gridDim.x - 1 - blockIdx.x;
    const int bh = blockIdx.y, b = bh >> 4, h = bh & 15;
    const size_t hb = (size_t)bh * SEQ * HD;

    const int lrow = lane & 15, lchk = lane >> 4;
    const int vsel = lane >> 3;
    const int vrow = (lane & 7) + ((vsel & 2) ? 8 : 0);
    const int vcol = (vsel & 1) ? 16 : 0;
    const int grp  = lane >> 2, cb = (lane & 3) * 2;

    {
        const char* qg  = (const char*)(qhi + hb + (size_t)qt * 128 * HD);
        const char* qg2 = (const char*)(qlo + hb + (size_t)qt * 128 * HD);
        #pragma unroll
        for (int it = 0; it < 4; it++) {
            int lin = it * 256 + tid;
            int r = lin >> 3, c = (lin & 7) * 16;
            uint32_t so = swz((uint32_t)(r * 128 + c));
            CP16(sb + so,         qg  + (size_t)r * 128 + c);
            CP16(sb + 16384 + so, qg2 + (size_t)r * 128 + c);
        }
    }
    load_kv(sb + 32768, khi + hb, klo + hb, vhi + hb, vlo + hb, 0, tid);
    CP_COMMIT();

    const int nit = 2 * qt + 2;
    float m0 = -INFINITY, m1 = -INFINITY, l0 = 0.f, l1 = 0.f;
    float oacc[8][4];
    #pragma unroll
    for (int jf = 0; jf < 8; jf++)
        #pragma unroll
        for (int e = 0; e < 4; e++) oacc[jf][e] = 0.f;

    const int rowg0 = qt*128 + wid*16 + grp;

    for (int j = 0; j < nit; j++) {
        const uint32_t st = sb + 32768 + (uint32_t)(j & 1) * 32768;
        CP_WAIT(0);
        __syncthreads();
        if (j + 1 < nit) {
            load_kv(sb + 32768 + (uint32_t)((j + 1) & 1) * 32768,
                    khi + hb, klo + hb, vhi + hb, vlo + hb, (j + 1) * 64, tid);
            CP_COMMIT();
        }

        if (j == 2*qt + 1 && wid < 4) continue;

        float sacc[8][4];
        #pragma unroll
        for (int jf = 0; jf < 8; jf++)
            #pragma unroll
            for (int e = 0; e < 4; e++) sacc[jf][e] = 0.f;

        #pragma unroll
        for (int kk = 0; kk < 4; kk++) {
            const uint32_t kb = (uint32_t)((kk*2 + lchk) * 16);
            const uint32_t ao = swz((uint32_t)((wid*16 + lrow) * 128) + kb);
            uint32_t ah[4], al[4];
            ldsm4(ah, sb + ao);
            ldsm4(al, sb + 16384 + ao);
            #pragma unroll
            for (int jn = 0; jn < 4; jn++) {
                const uint32_t bo = swz((uint32_t)((jn*16 + lrow) * 128) + kb);
                uint32_t bhh[4], bll[4];
                ldsm4(bhh, st + bo);
                ldsm4(bll, st + 8192 + bo);
                mma16816(sacc[2*jn],   ah, bhh[0], bhh[2]);
                mma16816(sacc[2*jn+1], ah, bhh[1], bhh[3]);
                mma16816(sacc[2*jn],   ah, bll[0], bll[2]);
                mma16816(sacc[2*jn+1], ah, bll[1], bll[3]);
                mma16816(sacc[2*jn],   al, bhh[0], bhh[2]);
                mma16816(sacc[2*jn+1], al, bhh[1], bhh[3]);
            }
        }

        if (j >= 2*qt) {
            #pragma unroll
            for (int jf = 0; jf < 8; jf++)
                #pragma unroll
                for (int e = 0; e < 4; e++) {
                    const int colg = j*64 + jf*8 + cb + (e & 1);
                    const int rowg = rowg0 + ((e >= 2) ? 8 : 0);
                    if (colg > rowg) sacc[jf][e] = -1e30f;
                }
        }

        float rmx0 = -3.0e30f, rmx1 = -3.0e30f;
        #pragma unroll
        for (int jf = 0; jf < 8; jf++) {
            rmx0 = fmaxf(rmx0, fmaxf(sacc[jf][0], sacc[jf][1]));
            rmx1 = fmaxf(rmx1, fmaxf(sacc[jf][2], sacc[jf][3]));
        }
        rmx0 = fmaxf(rmx0, __shfl_xor_sync(0xffffffffu, rmx0, 1));
        rmx0 = fmaxf(rmx0, __shfl_xor_sync(0xffffffffu, rmx0, 2));
        rmx1 = fmaxf(rmx1, __shfl_xor_sync(0xffffffffu, rmx1, 1));
        rmx1 = fmaxf(rmx1, __shfl_xor_sync(0xffffffffu, rmx1, 2));
        const float mn0 = fmaxf(m0, rmx0), mn1 = fmaxf(m1, rmx1);
        const float al0 = ex2(m0 - mn0), al1 = ex2(m1 - mn1);
        float rs0 = 0.f, rs1 = 0.f;
        #pragma unroll
        for (int jf = 0; jf < 8; jf++) {
            float p0 = ex2(sacc[jf][0] - mn0); sacc[jf][0] = p0; rs0 += p0;
            float p1 = ex2(sacc[jf][1] - mn0); sacc[jf][1] = p1; rs0 += p1;
            float p2 = ex2(sacc[jf][2] - mn1); sacc[jf][2] = p2; rs1 += p2;
            float p3 = ex2(sacc[jf][3] - mn1); sacc[jf][3] = p3; rs1 += p3;
        }
        l0 = l0*al0 + rs0; m0 = mn0;
        l1 = l1*al1 + rs1; m1 = mn1;
        #pragma unroll
        for (int jf = 0; jf < 8; jf++) {
            oacc[jf][0] *= al0; oacc[jf][1] *= al0;
            oacc[jf][2] *= al1; oacc[jf][3] *= al1;
        }

        #pragma unroll
        for (int tc = 0; tc < 4; tc++) {
            uint32_t ph[4];
            ph[0] = pack_h(sacc[2*tc][0],   sacc[2*tc][1]);
            ph[1] = pack_h(sacc[2*tc][2],   sacc[2*tc][3]);
            ph[2] = pack_h(sacc[2*tc+1][0], sacc[2*tc+1][1]);
            ph[3] = pack_h(sacc[2*tc+1][2], sacc[2*tc+1][3]);

            #pragma unroll
            for (int dn = 0; dn < 4; dn++) {
                const uint32_t ao = swz((uint32_t)((tc*16 + vrow) * 128 + dn*32 + vcol));
                uint32_t vh4[4], vl4[4];
                ldsm4t(vh4, st + 16384 + ao);
                ldsm4t(vl4, st + 24576 + ao);
                mma16816h(oacc[2*dn],   ph, vh4[0], vh4[2]);
                mma16816h(oacc[2*dn+1], ph, vh4[1], vh4[3]);
                mma16816h(oacc[2*dn],   ph, vl4[0], vl4[2]);
                mma16816h(oacc[2*dn+1], ph, vl4[1], vl4[3]);
            }
        }
    }

    l0 += __shfl_xor_sync(0xffffffffu, l0, 1);
    l0 += __shfl_xor_sync(0xffffffffu, l0, 2);
    l1 += __shfl_xor_sync(0xffffffffu, l1, 1);
    l1 += __shfl_xor_sync(0xffffffffu, l1, 2);

    const float inv0 = 1.f / l0, inv1 = 1.f / l1;
    #pragma unroll
    for (int jf = 0; jf < 8; jf++)
        #pragma unroll
        for (int e = 0; e < 4; e++) {
            const float o = oacc[jf][e] * ((e >= 2) ? inv1 : inv0);
            const int d  = jf*8 + cb + (e & 1);
            const int sg = qt*128 + wid*16 + grp + ((e >= 2) ? 8 : 0);
            const size_t off = ((size_t)b * SEQ + sg) * EMB + h*64 + d;
            oout[off] = __half_as_ushort(__float2half_rn(o));
        }
}

// ---------------------------------------------------------------------------
extern "C" void kernel_launch(void* const* d_in, const int* in_sizes, int n_in,
                              void* d_out, int out_size)
{
    const float* query = (const float*)d_in[0];
    const float* key   = (const float*)d_in[1];
    const float* value = (const float*)d_in[2];
    const float* Wq    = (const float*)d_in[3];
    const float* bq    = (const float*)d_in[4];
    const float* Wk    = (const float*)d_in[5];
    const float* bk    = (const float*)d_in[6];
    const float* Wv    = (const float*)d_in[7];
    const float* bv    = (const float*)d_in[8];
    const float* Wo    = (const float*)d_in[9];
    const float* bo    = (const float*)d_in[10];

    __nv_bfloat16 *qhi, *qlo, *khi, *klo, *vhi, *vlo, *ahi;
    cudaGetSymbolAddress((void**)&qhi, g_qhi);
    cudaGetSymbolAddress((void**)&qlo, g_qlo);
    cudaGetSymbolAddress((void**)&khi, g_khi);
    cudaGetSymbolAddress((void**)&klo, g_klo);
    cudaGetSymbolAddress((void**)&vhi, g_vhi);
    cudaGetSymbolAddress((void**)&vlo, g_vlo);
    cudaGetSymbolAddress((void**)&ahi, g_ahi);

    cudaFuncSetAttribute(tc_gemm_qk,
                         cudaFuncAttributeMaxDynamicSharedMemorySize, GSM3_TOTAL);
    cudaFuncSetAttribute(tc_gemm_v,
                         cudaFuncAttributeMaxDynamicSharedMemorySize, GSMH_TOTAL);
    cudaFuncSetAttribute(tc_gemm_o,
                         cudaFuncAttributeMaxDynamicSharedMemorySize, GSMH_TOTAL);
    cudaFuncSetAttribute(attn_tc,
                         cudaFuncAttributeMaxDynamicSharedMemorySize, ATT_TOTAL);

    split_all<<<dim3((int)(ANELEM/4)/2048, 1, 8), 256>>>(query, key, value,
                                                         Wq, Wk, Wv, Wo);

    tc_gemm_qk<<<dim3(EMB/64, MROWS/128, 2), 256, GSM3_TOTAL>>>(bq, bk);
    tc_gemm_v<<<dim3(EMB/64, MROWS/128), 256, GSMH_TOTAL>>>(bv);

    attn_tc<<<dim3(SEQ/128, BS_*NH), 256, ATT_TOTAL>>>(qhi, qlo, khi, klo,
                                                       vhi, vlo, (uint16_t*)ahi);

    tc_gemm_o<<<dim3(EMB/64, MROWS/128), 256, GSMH_TOTAL>>>(bo, (float*)d_out);
}

// round 16
// speedup vs baseline: 1.4156x; 1.4156x over previous
#include <cuda_runtime.h>
#include <cuda_bf16.h>
#include <cuda_fp16.h>
#include <math.h>
#include <stdint.h>

#define BS_  2
#define SEQ  2048
#define EMB  1024
#define NH   16
#define HD   64
#define MROWS (BS_*SEQ)   // 4096
#define ANELEM ((size_t)MROWS*EMB)
#define WNELEM ((size_t)EMB*EMB)

// ------------------------- scratch (__device__ globals) ---------------------
__device__ __nv_bfloat16 g_xhi[3*ANELEM];   // split activations q,k,v (bf16 hi/lo)
__device__ __nv_bfloat16 g_xlo[3*ANELEM];
__device__ __nv_bfloat16 g_whi[4*WNELEM];   // split weights Wq,Wk,Wv,Wo (bf16 hi/lo)
__device__ __nv_bfloat16 g_wlo[4*WNELEM];
__device__ __nv_bfloat16 g_qhi[ANELEM];     // roped+scaled Q [B,H,S,D] (bf16 hi/lo)
__device__ __nv_bfloat16 g_qlo[ANELEM];
__device__ __nv_bfloat16 g_khi[ANELEM];     // roped K (bf16 hi/lo)
__device__ __nv_bfloat16 g_klo[ANELEM];
__device__ __nv_bfloat16 g_vhi[ANELEM];     // V (fp16 hi/lo, raw bits)
__device__ __nv_bfloat16 g_vlo[ANELEM];
__device__ __nv_bfloat16 g_ahi[ANELEM];     // attention out (bf16 hi/lo)
__device__ __nv_bfloat16 g_alo[ANELEM];
__device__ float g_cs[SEQ*32];
__device__ float g_sn[SEQ*32];

// ------------------------- helpers ------------------------------------------
__device__ __forceinline__ uint32_t smem_u32(const void* p) {
    uint32_t a;
    asm("{ .reg .u64 t; cvta.to.shared.u64 t, %1; cvt.u32.u64 %0, t; }"
        : "=r"(a) : "l"(p));
    return a;
}
#define CP16(dst, src) \
    asm volatile("cp.async.cg.shared.global [%0], [%1], 16;" :: "r"(dst), "l"(src) : "memory")
#define CP_COMMIT() asm volatile("cp.async.commit_group;" ::: "memory")
#define CP_WAIT(n)  asm volatile("cp.async.wait_group %0;" :: "n"(n) : "memory")

__device__ __forceinline__ void ldsm4(uint32_t* r, uint32_t addr) {
    asm volatile("ldmatrix.sync.aligned.m8n8.x4.shared.b16 {%0,%1,%2,%3}, [%4];"
                 : "=r"(r[0]), "=r"(r[1]), "=r"(r[2]), "=r"(r[3]) : "r"(addr));
}
__device__ __forceinline__ void ldsm4t(uint32_t* r, uint32_t addr) {
    asm volatile("ldmatrix.sync.aligned.m8n8.x4.trans.shared.b16 {%0,%1,%2,%3}, [%4];"
                 : "=r"(r[0]), "=r"(r[1]), "=r"(r[2]), "=r"(r[3]) : "r"(addr));
}
__device__ __forceinline__ void mma16816(float* c, const uint32_t* a,
                                         uint32_t b0, uint32_t b1) {
    asm volatile("mma.sync.aligned.m16n8k16.row.col.f32.bf16.bf16.f32 "
                 "{%0,%1,%2,%3}, {%4,%5,%6,%7}, {%8,%9}, {%0,%1,%2,%3};"
                 : "+f"(c[0]), "+f"(c[1]), "+f"(c[2]), "+f"(c[3])
                 : "r"(a[0]), "r"(a[1]), "r"(a[2]), "r"(a[3]), "r"(b0), "r"(b1));
}
__device__ __forceinline__ void mma16816h(float* c, const uint32_t* a,
                                          uint32_t b0, uint32_t b1) {
    asm volatile("mma.sync.aligned.m16n8k16.row.col.f32.f16.f16.f32 "
                 "{%0,%1,%2,%3}, {%4,%5,%6,%7}, {%8,%9}, {%0,%1,%2,%3};"
                 : "+f"(c[0]), "+f"(c[1]), "+f"(c[2]), "+f"(c[3])
                 : "r"(a[0]), "r"(a[1]), "r"(a[2]), "r"(a[3]), "r"(b0), "r"(b1));
}
__device__ __forceinline__ uint32_t swz(uint32_t off) { return off ^ ((off >> 3) & 0x70); }
__device__ __forceinline__ uint32_t pack_h(float lo, float hi) {
    uint32_t r;
    asm("cvt.rn.f16x2.f32 %0, %1, %2;" : "=r"(r) : "f"(hi), "f"(lo));
    return r;
}
__device__ __forceinline__ float ex2(float x) {
    float r;
    asm("ex2.approx.ftz.f32 %0, %1;" : "=f"(r) : "f"(x));
    return r;
}

// ------------------------- fused splits + rope table -------------------------
// z in 0..6: bf16 hi/lo splits. z == 7: rope table.
__global__ __launch_bounds__(256) void split_all(
    const float* __restrict__ q, const float* __restrict__ k,
    const float* __restrict__ v, const float* __restrict__ wq,
    const float* __restrict__ wk, const float* __restrict__ wv,
    const float* __restrict__ wo)
{
    const int z = blockIdx.z;
    if (z == 7) {
        int i = blockIdx.x * 256 + threadIdx.x;
        if (i < SEQ*32) {
            int s = i >> 5, d = i & 31;
            float inv = exp2f(-(float)d * (13.287712379549449f / 32.0f));
            float sn, cs;
            sincosf((float)s * inv, &sn, &cs);
            g_cs[i] = cs; g_sn[i] = sn;
        }
        return;
    }
    const float* src;
    __nv_bfloat16 *hi, *lo;
    int n4;
    if (z < 3) {
        src = (z == 0) ? q : (z == 1) ? k : v;
        hi = g_xhi + (size_t)z * ANELEM;
        lo = g_xlo + (size_t)z * ANELEM;
        n4 = (int)(ANELEM / 4);
    } else {
        src = (z == 3) ? wq : (z == 4) ? wk : (z == 5) ? wv : wo;
        hi = g_whi + (size_t)(z - 3) * WNELEM;
        lo = g_wlo + (size_t)(z - 3) * WNELEM;
        n4 = (int)(WNELEM / 4);
    }
    const int base = blockIdx.x * 2048 + threadIdx.x;
    #pragma unroll
    for (int it = 0; it < 8; it++) {
        const int i = base + it * 256;
        if (i < n4) {
            float4 val = ((const float4*)src)[i];
            __nv_bfloat16 h[4], l[4];
            float vv[4] = {val.x, val.y, val.z, val.w};
            #pragma unroll
            for (int j = 0; j < 4; j++) {
                h[j] = __float2bfloat16(vv[j]);
                l[j] = __float2bfloat16(vv[j] - __bfloat162float(h[j]));
            }
            ((uint2*)hi)[i] = *(uint2*)h;
            ((uint2*)lo)[i] = *(uint2*)l;
        }
    }
}

// ------------------------- mma.sync GEMM core --------------------------------
// 128x64 CTA tile, Kc=64, 256 threads (8 warps: 4 M x 2 N), warp tile 32x32.
// Single-barrier 2-stage cp.async. bf16 3-pass compensation.
// emode 1: fp32 row-major. emode 2: rope + bf16 hi/lo scatter.
// emode 3: fp16 hi/lo scatter (V path).
#define GA_PART 16384
#define GB_PART 8192
#define GSM_STAGE (2*GA_PART + 2*GB_PART)   // 49152
#define GSM_TOTAL (2*GSM_STAGE)             // 98304
#define NSTAGE 16

__device__ __forceinline__ void load_tileA(uint32_t sdst, const __nv_bfloat16* g,
                                           int row0, int kc0, int tid)
{
    const __nv_bfloat16* gp = g + (size_t)row0 * EMB + kc0;
    #pragma unroll
    for (int it = 0; it < 4; it++) {
        int lin = it * 256 + tid;
        int r = lin >> 3, cq = (lin & 7) << 3;
        CP16(sdst + swz((uint32_t)(r * 128 + cq * 2)), gp + (size_t)r * EMB + cq);
    }
}
__device__ __forceinline__ void load_tileB(uint32_t sdst, const __nv_bfloat16* g,
                                           int row0, int kc0, int tid)
{
    const __nv_bfloat16* gp = g + (size_t)row0 * EMB + kc0;
    #pragma unroll
    for (int it = 0; it < 2; it++) {
        int lin = it * 256 + tid;
        int r = lin >> 3, cq = (lin & 7) << 3;
        CP16(sdst + swz((uint32_t)(r * 128 + cq * 2)), gp + (size_t)r * EMB + cq);
    }
}

__device__ __forceinline__ void gemm_core(
    const __nv_bfloat16* __restrict__ Ahi, const __nv_bfloat16* __restrict__ Alo,
    const __nv_bfloat16* __restrict__ Bhi, const __nv_bfloat16* __restrict__ Blo,
    const float* __restrict__ bias,
    __nv_bfloat16* __restrict__ Ch, __nv_bfloat16* __restrict__ Cl,
    float* __restrict__ Cf, int emode, float oscale)
{
    extern __shared__ char sm[];
    const uint32_t sbase = smem_u32(sm);
    const int tid  = threadIdx.x;
    const int wid  = tid >> 5, lane = tid & 31;
    const int wm   = wid >> 1, wn = wid & 1;
    const int bm   = blockIdx.y * 128, bn = blockIdx.x * 64;

    float acc[2][4][4];
    #pragma unroll
    for (int i = 0; i < 2; i++)
        #pragma unroll
        for (int j = 0; j < 4; j++)
            #pragma unroll
            for (int e = 0; e < 4; e++) acc[i][j][e] = 0.f;

    const int lrow = lane & 15;
    const int lchk = lane >> 4;
    uint32_t offA[2], offB[2];
    #pragma unroll
    for (int i = 0; i < 2; i++) offA[i] = (uint32_t)((wm*32 + i*16 + lrow) * 128);
    #pragma unroll
    for (int jg = 0; jg < 2; jg++) offB[jg] = (uint32_t)((wn*16 + jg*32 + lrow) * 128);

    {
        uint32_t buf = sbase;
        load_tileA(buf,                       Ahi, bm, 0, tid);
        load_tileA(buf + GA_PART,             Alo, bm, 0, tid);
        load_tileB(buf + 2*GA_PART,           Bhi, bn, 0, tid);
        load_tileB(buf + 2*GA_PART + GB_PART, Blo, bn, 0, tid);
        CP_COMMIT();
    }

    for (int s = 0; s < NSTAGE; s++) {
        const uint32_t cbuf = sbase + (uint32_t)(s & 1) * GSM_STAGE;
        CP_WAIT(0);
        __syncthreads();
        if (s + 1 < NSTAGE) {
            uint32_t buf = sbase + (uint32_t)((s + 1) & 1) * GSM_STAGE;
            int kc = (s + 1) * 64;
            load_tileA(buf,                       Ahi, bm, kc, tid);
            load_tileA(buf + GA_PART,             Alo, bm, kc, tid);
            load_tileB(buf + 2*GA_PART,           Bhi, bn, kc, tid);
            load_tileB(buf + 2*GA_PART + GB_PART, Blo, bn, kc, tid);
            CP_COMMIT();
        }

        #pragma unroll
        for (int kk = 0; kk < 4; kk++) {
            const uint32_t kb = (uint32_t)((kk*2 + lchk) * 16);
            uint32_t ah[2][4], al[2][4];
            #pragma unroll
            for (int i = 0; i < 2; i++) {
                ldsm4(ah[i], cbuf + swz(offA[i] + kb));
                ldsm4(al[i], cbuf + GA_PART + swz(offA[i] + kb));
            }
            #pragma unroll
            for (int jg = 0; jg < 2; jg++) {
                uint32_t bh[4], bl[4];
                ldsm4(bh, cbuf + 2*GA_PART + swz(offB[jg] + kb));
                ldsm4(bl, cbuf + 2*GA_PART + GB_PART + swz(offB[jg] + kb));
                #pragma unroll
                for (int i = 0; i < 2; i++) {
                    mma16816(acc[i][jg*2],   ah[i], bh[0], bh[2]);
                    mma16816(acc[i][jg*2+1], ah[i], bh[1], bh[3]);
                    mma16816(acc[i][jg*2],   ah[i], bl[0], bl[2]);
                    mma16816(acc[i][jg*2+1], ah[i], bl[1], bl[3]);
                    mma16816(acc[i][jg*2],   al[i], bh[0], bh[2]);
                    mma16816(acc[i][jg*2+1], al[i], bh[1], bh[3]);
                }
            }
        }
    }

    const int grp = lane >> 2;
    const int cpo = (lane & 3) * 2;
    #pragma unroll
    for (int i = 0; i < 2; i++) {
        #pragma unroll
        for (int half = 0; half < 2; half++) {
            const int row = bm + wm*32 + i*16 + grp + half*8;
            const int bb = row >> 11, ss = row & 2047;
            if (emode == 1) {
                #pragma unroll
                for (int jg = 0; jg < 2; jg++)
                    #pragma unroll
                    for (int t = 0; t < 2; t++) {
                        const int col = bn + wn*16 + jg*32 + t*8 + cpo;
                        Cf[(size_t)row * EMB + col]     = acc[i][jg*2+t][half*2]   + bias[col];
                        Cf[(size_t)row * EMB + col + 1] = acc[i][jg*2+t][half*2+1] + bias[col+1];
                    }
            } else if (emode == 2) {
                const int hh = bn >> 6;
                #pragma unroll
                for (int t = 0; t < 2; t++)
                    #pragma unroll
                    for (int e = 0; e < 2; e++) {
                        const int d  = wn*16 + t*8 + cpo + e;   // 0..31
                        const float x1 = acc[i][t][half*2+e]   + bias[bn + d];
                        const float x2 = acc[i][2+t][half*2+e] + bias[bn + d + 32];
                        const float cs = g_cs[ss*32 + d];
                        const float sn = g_sn[ss*32 + d];
                        const float y1 = (x1*cs - x2*sn) * oscale;
                        const float y2 = (x2*cs + x1*sn) * oscale;
                        const __nv_bfloat16 h1 = __float2bfloat16(y1);
                        const __nv_bfloat16 h2 = __float2bfloat16(y2);
                        const __nv_bfloat16 l1 = __float2bfloat16(y1 - __bfloat162float(h1));
                        const __nv_bfloat16 l2 = __float2bfloat16(y2 - __bfloat162float(h2));
                        const size_t base = (((size_t)bb*NH + hh)*SEQ + ss)*HD + d;
                        Ch[base]      = h1; Cl[base]      = l1;
                        Ch[base + 32] = h2; Cl[base + 32] = l2;
                    }
            } else {
                // emode 3: V — fp16 hi/lo (raw bits into the bf16-typed arrays)
                const int hh = bn >> 6;
                uint16_t* Chu = reinterpret_cast<uint16_t*>(Ch);
                uint16_t* Clu = reinterpret_cast<uint16_t*>(Cl);
                #pragma unroll
                for (int jg = 0; jg < 2; jg++)
                    #pragma unroll
                    for (int t = 0; t < 2; t++)
                        #pragma unroll
                        for (int e = 0; e < 2; e++) {
                            const int d = wn*16 + jg*32 + t*8 + cpo + e;
                            const float v = acc[i][jg*2+t][half*2+e] + bias[bn + d];
                            const __half hv = __float2half_rn(v);
                            const __half lv = __float2half_rn(v - __half2float(hv));
                            const size_t base = (((size_t)bb*NH + hh)*SEQ + ss)*HD + d;
                            Chu[base] = __half_as_ushort(hv);
                            Clu[base] = __half_as_ushort(lv);
                        }
            }
        }
    }
}

#define QSCL 0.18033688011112042f   // (1/8) * log2(e)

__global__ __launch_bounds__(256, 2) void tc_gemm_qkv(
    const float* __restrict__ bq, const float* __restrict__ bk,
    const float* __restrict__ bv)
{
    const int z = blockIdx.z;
    const __nv_bfloat16* Ahi = g_xhi + (size_t)z * ANELEM;
    const __nv_bfloat16* Alo = g_xlo + (size_t)z * ANELEM;
    const __nv_bfloat16* Bhi = g_whi + (size_t)z * WNELEM;
    const __nv_bfloat16* Blo = g_wlo + (size_t)z * WNELEM;
    const float* bias = (z == 0) ? bq : (z == 1) ? bk : bv;
    __nv_bfloat16* Ch = (z == 0) ? g_qhi : (z == 1) ? g_khi : g_vhi;
    __nv_bfloat16* Cl = (z == 0) ? g_qlo : (z == 1) ? g_klo : g_vlo;
    const float osc = (z == 0) ? QSCL : 1.0f;
    gemm_core(Ahi, Alo, Bhi, Blo, bias, Ch, Cl, nullptr, (z == 2) ? 3 : 2, osc);
}

__global__ __launch_bounds__(256, 2) void tc_gemm_o(const float* __restrict__ bo,
                                                    float* __restrict__ out)
{
    gemm_core(g_ahi, g_alo, g_whi + 3*WNELEM, g_wlo + 3*WNELEM, bo,
              nullptr, nullptr, out, 1, 1.0f);
}

// ------------------------- tensor-core flash attention -----------------------
// QK: bf16 3-pass (log2 domain, Q pre-scaled). PV: fp16 2-pass (P single fp16,
// V fp16 hi/lo). Output: bf16 hi/lo.
#define ATT_TOTAL (32768 + 2*32768)

__device__ __forceinline__ void load_kv(uint32_t st,
    const __nv_bfloat16* kh, const __nv_bfloat16* kl,
    const __nv_bfloat16* vh, const __nv_bfloat16* vl, int t0, int tid)
{
    #pragma unroll
    for (int it = 0; it < 2; it++) {
        int lin = it * 256 + tid;
        int r = lin >> 3, c = (lin & 7) * 16;
        uint32_t so = swz((uint32_t)(r * 128 + c));
        size_t go = (size_t)(t0 + r) * 128 + c;
        CP16(st + so,          (const char*)kh + go);
        CP16(st + 8192 + so,   (const char*)kl + go);
        CP16(st + 16384 + so,  (const char*)vh + go);
        CP16(st + 24576 + so,  (const char*)vl + go);
    }
}

__global__ __launch_bounds__(256, 2) void attn_tc(
    const __nv_bfloat16* __restrict__ qhi, const __nv_bfloat16* __restrict__ qlo,
    const __nv_bfloat16* __restrict__ khi, const __nv_bfloat16* __restrict__ klo,
    const __nv_bfloat16* __restrict__ vhi, const __nv_bfloat16* __restrict__ vlo,
    __nv_bfloat16* __restrict__ ohi, __nv_bfloat16* __restrict__ olo)
{
    extern __shared__ char sm[];
    const uint32_t sb = smem_u32(sm);
    const int tid = threadIdx.x, wid = tid >> 5, lane = tid & 31;
    const int qt = gridDim.x - 1 - blockIdx.x;
    const int bh = blockIdx.y, b = bh >> 4, h = bh & 15;
    const size_t hb = (size_t)bh * SEQ * HD;

    const int lrow = lane & 15, lchk = lane >> 4;
    const int vsel = lane >> 3;
    const int vrow = (lane & 7) + ((vsel & 2) ? 8 : 0);
    const int vcol = (vsel & 1) ? 16 : 0;
    const int grp  = lane >> 2, cb = (lane & 3) * 2;

    {
        const char* qg  = (const char*)(qhi + hb + (size_t)qt * 128 * HD);
        const char* qg2 = (const char*)(qlo + hb + (size_t)qt * 128 * HD);
        #pragma unroll
        for (int it = 0; it < 4; it++) {
            int lin = it * 256 + tid;
            int r = lin >> 3, c = (lin & 7) * 16;
            uint32_t so = swz((uint32_t)(r * 128 + c));
            CP16(sb + so,         qg  + (size_t)r * 128 + c);
            CP16(sb + 16384 + so, qg2 + (size_t)r * 128 + c);
        }
    }
    load_kv(sb + 32768, khi + hb, klo + hb, vhi + hb, vlo + hb, 0, tid);
    CP_COMMIT();

    const int nit = 2 * qt + 2;
    float m0 = -INFINITY, m1 = -INFINITY, l0 = 0.f, l1 = 0.f;
    float oacc[8][4];
    #pragma unroll
    for (int jf = 0; jf < 8; jf++)
        #pragma unroll
        for (int e = 0; e < 4; e++) oacc[jf][e] = 0.f;

    const int rowg0 = qt*128 + wid*16 + grp;

    for (int j = 0; j < nit; j++) {
        const uint32_t st = sb + 32768 + (uint32_t)(j & 1) * 32768;
        CP_WAIT(0);
        __syncthreads();
        if (j + 1 < nit) {
            load_kv(sb + 32768 + (uint32_t)((j + 1) & 1) * 32768,
                    khi + hb, klo + hb, vhi + hb, vlo + hb, (j + 1) * 64, tid);
            CP_COMMIT();
        }

        if (j == 2*qt + 1 && wid < 4) continue;

        float sacc[8][4];
        #pragma unroll
        for (int jf = 0; jf < 8; jf++)
            #pragma unroll
            for (int e = 0; e < 4; e++) sacc[jf][e] = 0.f;

        #pragma unroll
        for (int kk = 0; kk < 4; kk++) {
            const uint32_t kb = (uint32_t)((kk*2 + lchk) * 16);
            const uint32_t ao = swz((uint32_t)((wid*16 + lrow) * 128) + kb);
            uint32_t ah[4], al[4];
            ldsm4(ah, sb + ao);
            ldsm4(al, sb + 16384 + ao);
            #pragma unroll
            for (int jn = 0; jn < 4; jn++) {
                const uint32_t bo = swz((uint32_t)((jn*16 + lrow) * 128) + kb);
                uint32_t bhh[4], bll[4];
                ldsm4(bhh, st + bo);
                ldsm4(bll, st + 8192 + bo);
                mma16816(sacc[2*jn],   ah, bhh[0], bhh[2]);
                mma16816(sacc[2*jn+1], ah, bhh[1], bhh[3]);
                mma16816(sacc[2*jn],   ah, bll[0], bll[2]);
                mma16816(sacc[2*jn+1], ah, bll[1], bll[3]);
                mma16816(sacc[2*jn],   al, bhh[0], bhh[2]);
                mma16816(sacc[2*jn+1], al, bhh[1], bhh[3]);
            }
        }

        if (j >= 2*qt) {
            #pragma unroll
            for (int jf = 0; jf < 8; jf++)
                #pragma unroll
                for (int e = 0; e < 4; e++) {
                    const int colg = j*64 + jf*8 + cb + (e & 1);
                    const int rowg = rowg0 + ((e >= 2) ? 8 : 0);
                    if (colg > rowg) sacc[jf][e] = -1e30f;
                }
        }

        float rmx0 = -3.0e30f, rmx1 = -3.0e30f;
        #pragma unroll
        for (int jf = 0; jf < 8; jf++) {
            rmx0 = fmaxf(rmx0, fmaxf(sacc[jf][0], sacc[jf][1]));
            rmx1 = fmaxf(rmx1, fmaxf(sacc[jf][2], sacc[jf][3]));
        }
        rmx0 = fmaxf(rmx0, __shfl_xor_sync(0xffffffffu, rmx0, 1));
        rmx0 = fmaxf(rmx0, __shfl_xor_sync(0xffffffffu, rmx0, 2));
        rmx1 = fmaxf(rmx1, __shfl_xor_sync(0xffffffffu, rmx1, 1));
        rmx1 = fmaxf(rmx1, __shfl_xor_sync(0xffffffffu, rmx1, 2));
        const float mn0 = fmaxf(m0, rmx0), mn1 = fmaxf(m1, rmx1);
        const float al0 = ex2(m0 - mn0), al1 = ex2(m1 - mn1);
        float rs0 = 0.f, rs1 = 0.f;
        #pragma unroll
        for (int jf = 0; jf < 8; jf++) {
            float p0 = ex2(sacc[jf][0] - mn0); sacc[jf][0] = p0; rs0 += p0;
            float p1 = ex2(sacc[jf][1] - mn0); sacc[jf][1] = p1; rs0 += p1;
            float p2 = ex2(sacc[jf][2] - mn1); sacc[jf][2] = p2; rs1 += p2;
            float p3 = ex2(sacc[jf][3] - mn1); sacc[jf][3] = p3; rs1 += p3;
        }
        l0 = l0*al0 + rs0; m0 = mn0;
        l1 = l1*al1 + rs1; m1 = mn1;
        #pragma unroll
        for (int jf = 0; jf < 8; jf++) {
            oacc[jf][0] *= al0; oacc[jf][1] *= al0;
            oacc[jf][2] *= al1; oacc[jf][3] *= al1;
        }

        // ---- O += P V (fp16: P single operand, V hi/lo) ----
        #pragma unroll
        for (int tc = 0; tc < 4; tc++) {
            uint32_t ph[4];
            ph[0] = pack_h(sacc[2*tc][0],   sacc[2*tc][1]);
            ph[1] = pack_h(sacc[2*tc][2],   sacc[2*tc][3]);
            ph[2] = pack_h(sacc[2*tc+1][0], sacc[2*tc+1][1]);
            ph[3] = pack_h(sacc[2*tc+1][2], sacc[2*tc+1][3]);

            #pragma unroll
            for (int dn = 0; dn < 4; dn++) {
                const uint32_t ao = swz((uint32_t)((tc*16 + vrow) * 128 + dn*32 + vcol));
                uint32_t vh4[4], vl4[4];
                ldsm4t(vh4, st + 16384 + ao);
                ldsm4t(vl4, st + 24576 + ao);
                mma16816h(oacc[2*dn],   ph, vh4[0], vh4[2]);
                mma16816h(oacc[2*dn+1], ph, vh4[1], vh4[3]);
                mma16816h(oacc[2*dn],   ph, vl4[0], vl4[2]);
                mma16816h(oacc[2*dn+1], ph, vl4[1], vl4[3]);
            }
        }
    }

    l0 += __shfl_xor_sync(0xffffffffu, l0, 1);
    l0 += __shfl_xor_sync(0xffffffffu, l0, 2);
    l1 += __shfl_xor_sync(0xffffffffu, l1, 1);
    l1 += __shfl_xor_sync(0xffffffffu, l1, 2);

    const float inv0 = 1.f / l0, inv1 = 1.f / l1;
    #pragma unroll
    for (int jf = 0; jf < 8; jf++)
        #pragma unroll
        for (int e = 0; e < 4; e++) {
            const float o = oacc[jf][e] * ((e >= 2) ? inv1 : inv0);
            const int d  = jf*8 + cb + (e & 1);
            const int sg = qt*128 + wid*16 + grp + ((e >= 2) ? 8 : 0);
            const __nv_bfloat16 hv = __float2bfloat16(o);
            const __nv_bfloat16 lv = __float2bfloat16(o - __bfloat162float(hv));
            const size_t off = ((size_t)b * SEQ + sg) * EMB + h*64 + d;
            ohi[off] = hv; olo[off] = lv;
        }
}

// ---------------------------------------------------------------------------
extern "C" void kernel_launch(void* const* d_in, const int* in_sizes, int n_in,
                              void* d_out, int out_size)
{
    const float* query = (const float*)d_in[0];
    const float* key   = (const float*)d_in[1];
    const float* value = (const float*)d_in[2];
    const float* Wq    = (const float*)d_in[3];
    const float* bq    = (const float*)d_in[4];
    const float* Wk    = (const float*)d_in[5];
    const float* bk    = (const float*)d_in[6];
    const float* Wv    = (const float*)d_in[7];
    const float* bv    = (const float*)d_in[8];
    const float* Wo    = (const float*)d_in[9];
    const float* bo    = (const float*)d_in[10];

    __nv_bfloat16 *qhi, *qlo, *khi, *klo, *vhi, *vlo, *ahi, *alo;
    cudaGetSymbolAddress((void**)&qhi, g_qhi);
    cudaGetSymbolAddress((void**)&qlo, g_qlo);
    cudaGetSymbolAddress((void**)&khi, g_khi);
    cudaGetSymbolAddress((void**)&klo, g_klo);
    cudaGetSymbolAddress((void**)&vhi, g_vhi);
    cudaGetSymbolAddress((void**)&vlo, g_vlo);
    cudaGetSymbolAddress((void**)&ahi, g_ahi);
    cudaGetSymbolAddress((void**)&alo, g_alo);

    cudaFuncSetAttribute(tc_gemm_qkv,
                         cudaFuncAttributeMaxDynamicSharedMemorySize, GSM_TOTAL);
    cudaFuncSetAttribute(tc_gemm_o,
                         cudaFuncAttributeMaxDynamicSharedMemorySize, GSM_TOTAL);
    cudaFuncSetAttribute(attn_tc,
                         cudaFuncAttributeMaxDynamicSharedMemorySize, ATT_TOTAL);

    split_all<<<dim3((int)(ANELEM/4)/2048, 1, 8), 256>>>(query, key, value,
                                                         Wq, Wk, Wv, Wo);

    tc_gemm_qkv<<<dim3(EMB/64, MROWS/128, 3), 256, GSM_TOTAL>>>(bq, bk, bv);

    attn_tc<<<dim3(SEQ/128, BS_*NH), 256, ATT_TOTAL>>>(qhi, qlo, khi, klo,
                                                       vhi, vlo, ahi, alo);

    tc_gemm_o<<<dim3(EMB/64, MROWS/128), 256, GSM_TOTAL>>>(bo, (float*)d_out);
}

// round 17
// speedup vs baseline: 1.5326x; 1.0827x over previous
#include <cuda_runtime.h>
#include <cuda_bf16.h>
#include <cuda_fp16.h>
#include <math.h>
#include <stdint.h>

#define BS_  2
#define SEQ  2048
#define EMB  1024
#define NH   16
#define HD   64
#define MROWS (BS_*SEQ)   // 4096
#define ANELEM ((size_t)MROWS*EMB)
#define WNELEM ((size_t)EMB*EMB)

// ------------------------- scratch (__device__ globals) ---------------------
__device__ __nv_bfloat16 g_xhi[3*ANELEM];   // split activations q,k,v (bf16 hi/lo)
__device__ __nv_bfloat16 g_xlo[3*ANELEM];
__device__ __nv_bfloat16 g_whi[4*WNELEM];   // split weights Wq,Wk,Wv,Wo (bf16 hi/lo)
__device__ __nv_bfloat16 g_wlo[4*WNELEM];
__device__ __nv_bfloat16 g_qhi[ANELEM];     // roped+scaled Q [B,H,S,D] (bf16 hi/lo)
__device__ __nv_bfloat16 g_qlo[ANELEM];
__device__ __nv_bfloat16 g_khi[ANELEM];     // roped K (bf16 hi/lo)
__device__ __nv_bfloat16 g_klo[ANELEM];
__device__ __nv_bfloat16 g_vhi[ANELEM];     // V (single fp16, raw bits)
__device__ __nv_bfloat16 g_ahi[ANELEM];     // attention out (bf16 hi/lo)
__device__ __nv_bfloat16 g_alo[ANELEM];
__device__ float g_cs[SEQ*32];
__device__ float g_sn[SEQ*32];

// ------------------------- helpers ------------------------------------------
__device__ __forceinline__ uint32_t smem_u32(const void* p) {
    uint32_t a;
    asm("{ .reg .u64 t; cvta.to.shared.u64 t, %1; cvt.u32.u64 %0, t; }"
        : "=r"(a) : "l"(p));
    return a;
}
#define CP16(dst, src) \
    asm volatile("cp.async.cg.shared.global [%0], [%1], 16;" :: "r"(dst), "l"(src) : "memory")
#define CP_COMMIT() asm volatile("cp.async.commit_group;" ::: "memory")
#define CP_WAIT(n)  asm volatile("cp.async.wait_group %0;" :: "n"(n) : "memory")

__device__ __forceinline__ void ldsm4(uint32_t* r, uint32_t addr) {
    asm volatile("ldmatrix.sync.aligned.m8n8.x4.shared.b16 {%0,%1,%2,%3}, [%4];"
                 : "=r"(r[0]), "=r"(r[1]), "=r"(r[2]), "=r"(r[3]) : "r"(addr));
}
__device__ __forceinline__ void ldsm4t(uint32_t* r, uint32_t addr) {
    asm volatile("ldmatrix.sync.aligned.m8n8.x4.trans.shared.b16 {%0,%1,%2,%3}, [%4];"
                 : "=r"(r[0]), "=r"(r[1]), "=r"(r[2]), "=r"(r[3]) : "r"(addr));
}
__device__ __forceinline__ void mma16816(float* c, const uint32_t* a,
                                         uint32_t b0, uint32_t b1) {
    asm volatile("mma.sync.aligned.m16n8k16.row.col.f32.bf16.bf16.f32 "
                 "{%0,%1,%2,%3}, {%4,%5,%6,%7}, {%8,%9}, {%0,%1,%2,%3};"
                 : "+f"(c[0]), "+f"(c[1]), "+f"(c[2]), "+f"(c[3])
                 : "r"(a[0]), "r"(a[1]), "r"(a[2]), "r"(a[3]), "r"(b0), "r"(b1));
}
__device__ __forceinline__ void mma16816h(float* c, const uint32_t* a,
                                          uint32_t b0, uint32_t b1) {
    asm volatile("mma.sync.aligned.m16n8k16.row.col.f32.f16.f16.f32 "
                 "{%0,%1,%2,%3}, {%4,%5,%6,%7}, {%8,%9}, {%0,%1,%2,%3};"
                 : "+f"(c[0]), "+f"(c[1]), "+f"(c[2]), "+f"(c[3])
                 : "r"(a[0]), "r"(a[1]), "r"(a[2]), "r"(a[3]), "r"(b0), "r"(b1));
}
__device__ __forceinline__ uint32_t swz(uint32_t off) { return off ^ ((off >> 3) & 0x70); }
__device__ __forceinline__ uint32_t pack_h(float lo, float hi) {
    uint32_t r;
    asm("cvt.rn.f16x2.f32 %0, %1, %2;" : "=r"(r) : "f"(hi), "f"(lo));
    return r;
}
__device__ __forceinline__ float ex2(float x) {
    float r;
    asm("ex2.approx.ftz.f32 %0, %1;" : "=f"(r) : "f"(x));
    return r;
}

// ------------------------- fused splits + rope table -------------------------
// z in 0..6: bf16 hi/lo splits. z == 7: rope table.
__global__ __launch_bounds__(256) void split_all(
    const float* __restrict__ q, const float* __restrict__ k,
    const float* __restrict__ v, const float* __restrict__ wq,
    const float* __restrict__ wk, const float* __restrict__ wv,
    const float* __restrict__ wo)
{
    const int z = blockIdx.z;
    if (z == 7) {
        int i = blockIdx.x * 256 + threadIdx.x;
        if (i < SEQ*32) {
            int s = i >> 5, d = i & 31;
            float inv = exp2f(-(float)d * (13.287712379549449f / 32.0f));
            float sn, cs;
            sincosf((float)s * inv, &sn, &cs);
            g_cs[i] = cs; g_sn[i] = sn;
        }
        return;
    }
    const float* src;
    __nv_bfloat16 *hi, *lo;
    int n4;
    if (z < 3) {
        src = (z == 0) ? q : (z == 1) ? k : v;
        hi = g_xhi + (size_t)z * ANELEM;
        lo = g_xlo + (size_t)z * ANELEM;
        n4 = (int)(ANELEM / 4);
    } else {
        src = (z == 3) ? wq : (z == 4) ? wk : (z == 5) ? wv : wo;
        hi = g_whi + (size_t)(z - 3) * WNELEM;
        lo = g_wlo + (size_t)(z - 3) * WNELEM;
        n4 = (int)(WNELEM / 4);
    }
    const int base = blockIdx.x * 2048 + threadIdx.x;
    #pragma unroll
    for (int it = 0; it < 8; it++) {
        const int i = base + it * 256;
        if (i < n4) {
            float4 val = ((const float4*)src)[i];
            __nv_bfloat16 h[4], l[4];
            float vv[4] = {val.x, val.y, val.z, val.w};
            #pragma unroll
            for (int j = 0; j < 4; j++) {
                h[j] = __float2bfloat16(vv[j]);
                l[j] = __float2bfloat16(vv[j] - __bfloat162float(h[j]));
            }
            ((uint2*)hi)[i] = *(uint2*)h;
            ((uint2*)lo)[i] = *(uint2*)l;
        }
    }
}

// ------------------------- mma.sync GEMM core --------------------------------
// 128x64 CTA tile, Kc=64, 256 threads (8 warps: 4 M x 2 N), warp tile 32x32.
// Single-barrier 2-stage cp.async. bf16 3-pass compensation.
// emode 1: fp32 row-major. emode 2: rope + bf16 hi/lo scatter.
// emode 3: single-fp16 scatter (V path).
#define GA_PART 16384
#define GB_PART 8192
#define GSM_STAGE (2*GA_PART + 2*GB_PART)   // 49152
#define GSM_TOTAL (2*GSM_STAGE)             // 98304
#define NSTAGE 16

__device__ __forceinline__ void load_tileA(uint32_t sdst, const __nv_bfloat16* g,
                                           int row0, int kc0, int tid)
{
    const __nv_bfloat16* gp = g + (size_t)row0 * EMB + kc0;
    #pragma unroll
    for (int it = 0; it < 4; it++) {
        int lin = it * 256 + tid;
        int r = lin >> 3, cq = (lin & 7) << 3;
        CP16(sdst + swz((uint32_t)(r * 128 + cq * 2)), gp + (size_t)r * EMB + cq);
    }
}
__device__ __forceinline__ void load_tileB(uint32_t sdst, const __nv_bfloat16* g,
                                           int row0, int kc0, int tid)
{
    const __nv_bfloat16* gp = g + (size_t)row0 * EMB + kc0;
    #pragma unroll
    for (int it = 0; it < 2; it++) {
        int lin = it * 256 + tid;
        int r = lin >> 3, cq = (lin & 7) << 3;
        CP16(sdst + swz((uint32_t)(r * 128 + cq * 2)), gp + (size_t)r * EMB + cq);
    }
}

__device__ __forceinline__ void gemm_core(
    const __nv_bfloat16* __restrict__ Ahi, const __nv_bfloat16* __restrict__ Alo,
    const __nv_bfloat16* __restrict__ Bhi, const __nv_bfloat16* __restrict__ Blo,
    const float* __restrict__ bias,
    __nv_bfloat16* __restrict__ Ch, __nv_bfloat16* __restrict__ Cl,
    float* __restrict__ Cf, int emode, float oscale)
{
    extern __shared__ char sm[];
    const uint32_t sbase = smem_u32(sm);
    const int tid  = threadIdx.x;
    const int wid  = tid >> 5, lane = tid & 31;
    const int wm   = wid >> 1, wn = wid & 1;
    const int bm   = blockIdx.y * 128, bn = blockIdx.x * 64;

    float acc[2][4][4];
    #pragma unroll
    for (int i = 0; i < 2; i++)
        #pragma unroll
        for (int j = 0; j < 4; j++)
            #pragma unroll
            for (int e = 0; e < 4; e++) acc[i][j][e] = 0.f;

    const int lrow = lane & 15;
    const int lchk = lane >> 4;
    uint32_t offA[2], offB[2];
    #pragma unroll
    for (int i = 0; i < 2; i++) offA[i] = (uint32_t)((wm*32 + i*16 + lrow) * 128);
    #pragma unroll
    for (int jg = 0; jg < 2; jg++) offB[jg] = (uint32_t)((wn*16 + jg*32 + lrow) * 128);

    {
        uint32_t buf = sbase;
        load_tileA(buf,                       Ahi, bm, 0, tid);
        load_tileA(buf + GA_PART,             Alo, bm, 0, tid);
        load_tileB(buf + 2*GA_PART,           Bhi, bn, 0, tid);
        load_tileB(buf + 2*GA_PART + GB_PART, Blo, bn, 0, tid);
        CP_COMMIT();
    }

    for (int s = 0; s < NSTAGE; s++) {
        const uint32_t cbuf = sbase + (uint32_t)(s & 1) * GSM_STAGE;
        CP_WAIT(0);
        __syncthreads();
        if (s + 1 < NSTAGE) {
            uint32_t buf = sbase + (uint32_t)((s + 1) & 1) * GSM_STAGE;
            int kc = (s + 1) * 64;
            load_tileA(buf,                       Ahi, bm, kc, tid);
            load_tileA(buf + GA_PART,             Alo, bm, kc, tid);
            load_tileB(buf + 2*GA_PART,           Bhi, bn, kc, tid);
            load_tileB(buf + 2*GA_PART + GB_PART, Blo, bn, kc, tid);
            CP_COMMIT();
        }

        #pragma unroll
        for (int kk = 0; kk < 4; kk++) {
            const uint32_t kb = (uint32_t)((kk*2 + lchk) * 16);
            uint32_t ah[2][4], al[2][4];
            #pragma unroll
            for (int i = 0; i < 2; i++) {
                ldsm4(ah[i], cbuf + swz(offA[i] + kb));
                ldsm4(al[i], cbuf + GA_PART + swz(offA[i] + kb));
            }
            #pragma unroll
            for (int jg = 0; jg < 2; jg++) {
                uint32_t bh[4], bl[4];
                ldsm4(bh, cbuf + 2*GA_PART + swz(offB[jg] + kb));
                ldsm4(bl, cbuf + 2*GA_PART + GB_PART + swz(offB[jg] + kb));
                #pragma unroll
                for (int i = 0; i < 2; i++) {
                    mma16816(acc[i][jg*2],   ah[i], bh[0], bh[2]);
                    mma16816(acc[i][jg*2+1], ah[i], bh[1], bh[3]);
                    mma16816(acc[i][jg*2],   ah[i], bl[0], bl[2]);
                    mma16816(acc[i][jg*2+1], ah[i], bl[1], bl[3]);
                    mma16816(acc[i][jg*2],   al[i], bh[0], bh[2]);
                    mma16816(acc[i][jg*2+1], al[i], bh[1], bh[3]);
                }
            }
        }
    }

    const int grp = lane >> 2;
    const int cpo = (lane & 3) * 2;
    #pragma unroll
    for (int i = 0; i < 2; i++) {
        #pragma unroll
        for (int half = 0; half < 2; half++) {
            const int row = bm + wm*32 + i*16 + grp + half*8;
            const int bb = row >> 11, ss = row & 2047;
            if (emode == 1) {
                #pragma unroll
                for (int jg = 0; jg < 2; jg++)
                    #pragma unroll
                    for (int t = 0; t < 2; t++) {
                        const int col = bn + wn*16 + jg*32 + t*8 + cpo;
                        Cf[(size_t)row * EMB + col]     = acc[i][jg*2+t][half*2]   + bias[col];
                        Cf[(size_t)row * EMB + col + 1] = acc[i][jg*2+t][half*2+1] + bias[col+1];
                    }
            } else if (emode == 2) {
                const int hh = bn >> 6;
                #pragma unroll
                for (int t = 0; t < 2; t++)
                    #pragma unroll
                    for (int e = 0; e < 2; e++) {
                        const int d  = wn*16 + t*8 + cpo + e;   // 0..31
                        const float x1 = acc[i][t][half*2+e]   + bias[bn + d];
                        const float x2 = acc[i][2+t][half*2+e] + bias[bn + d + 32];
                        const float cs = g_cs[ss*32 + d];
                        const float sn = g_sn[ss*32 + d];
                        const float y1 = (x1*cs - x2*sn) * oscale;
                        const float y2 = (x2*cs + x1*sn) * oscale;
                        const __nv_bfloat16 h1 = __float2bfloat16(y1);
                        const __nv_bfloat16 h2 = __float2bfloat16(y2);
                        const __nv_bfloat16 l1 = __float2bfloat16(y1 - __bfloat162float(h1));
                        const __nv_bfloat16 l2 = __float2bfloat16(y2 - __bfloat162float(h2));
                        const size_t base = (((size_t)bb*NH + hh)*SEQ + ss)*HD + d;
                        Ch[base]      = h1; Cl[base]      = l1;
                        Ch[base + 32] = h2; Cl[base + 32] = l2;
                    }
            } else {
                // emode 3: V — single fp16 (raw bits into the bf16-typed array)
                const int hh = bn >> 6;
                uint16_t* Chu = reinterpret_cast<uint16_t*>(Ch);
                #pragma unroll
                for (int jg = 0; jg < 2; jg++)
                    #pragma unroll
                    for (int t = 0; t < 2; t++)
                        #pragma unroll
                        for (int e = 0; e < 2; e++) {
                            const int d = wn*16 + jg*32 + t*8 + cpo + e;
                            const float v = acc[i][jg*2+t][half*2+e] + bias[bn + d];
                            const size_t base = (((size_t)bb*NH + hh)*SEQ + ss)*HD + d;
                            Chu[base] = __half_as_ushort(__float2half_rn(v));
                        }
            }
        }
    }
}

#define QSCL 0.18033688011112042f   // (1/8) * log2(e)

__global__ __launch_bounds__(256, 2) void tc_gemm_qkv(
    const float* __restrict__ bq, const float* __restrict__ bk,
    const float* __restrict__ bv)
{
    const int z = blockIdx.z;
    const __nv_bfloat16* Ahi = g_xhi + (size_t)z * ANELEM;
    const __nv_bfloat16* Alo = g_xlo + (size_t)z * ANELEM;
    const __nv_bfloat16* Bhi = g_whi + (size_t)z * WNELEM;
    const __nv_bfloat16* Blo = g_wlo + (size_t)z * WNELEM;
    const float* bias = (z == 0) ? bq : (z == 1) ? bk : bv;
    __nv_bfloat16* Ch = (z == 0) ? g_qhi : (z == 1) ? g_khi : g_vhi;
    __nv_bfloat16* Cl = (z == 0) ? g_qlo : (z == 1) ? g_klo : nullptr;
    const float osc = (z == 0) ? QSCL : 1.0f;
    gemm_core(Ahi, Alo, Bhi, Blo, bias, Ch, Cl, nullptr, (z == 2) ? 3 : 2, osc);
}

__global__ __launch_bounds__(256, 2) void tc_gemm_o(const float* __restrict__ bo,
                                                    float* __restrict__ out)
{
    gemm_core(g_ahi, g_alo, g_whi + 3*WNELEM, g_wlo + 3*WNELEM, bo,
              nullptr, nullptr, out, 1, 1.0f);
}

// ------------------------- tensor-core flash attention -----------------------
// QK: bf16 3-pass (log2 domain, Q pre-scaled). PV: fp16 single-pass
// (P single fp16, V single fp16). Output: bf16 hi/lo.
#define KV_STAGE 24576                       // K hi 8K + K lo 8K + V 8K
#define ATT_TOTAL (32768 + 2*KV_STAGE)       // 81920

__device__ __forceinline__ void load_kv(uint32_t st,
    const __nv_bfloat16* kh, const __nv_bfloat16* kl,
    const __nv_bfloat16* vh, int t0, int tid)
{
    #pragma unroll
    for (int it = 0; it < 2; it++) {
        int lin = it * 256 + tid;
        int r = lin >> 3, c = (lin & 7) * 16;
        uint32_t so = swz((uint32_t)(r * 128 + c));
        size_t go = (size_t)(t0 + r) * 128 + c;
        CP16(st + so,          (const char*)kh + go);
        CP16(st + 8192 + so,   (const char*)kl + go);
        CP16(st + 16384 + so,  (const char*)vh + go);
    }
}

__global__ __launch_bounds__(256, 2) void attn_tc(
    const __nv_bfloat16* __restrict__ qhi, const __nv_bfloat16* __restrict__ qlo,
    const __nv_bfloat16* __restrict__ khi, const __nv_bfloat16* __restrict__ klo,
    const __nv_bfloat16* __restrict__ vhi,
    __nv_bfloat16* __restrict__ ohi, __nv_bfloat16* __restrict__ olo)
{
    extern __shared__ char sm[];
    const uint32_t sb = smem_u32(sm);
    const int tid = threadIdx.x, wid = tid >> 5, lane = tid & 31;
    const int qt = gridDim.x - 1 - blockIdx.x;
    const int bh = blockIdx.y, b = bh >> 4, h = bh & 15;
    const size_t hb = (size_t)bh * SEQ * HD;

    const int lrow = lane & 15, lchk = lane >> 4;
    const int vsel = lane >> 3;
    const int vrow = (lane & 7) + ((vsel & 2) ? 8 : 0);
    const int vcol = (vsel & 1) ? 16 : 0;
    const int grp  = lane >> 2, cb = (lane & 3) * 2;

    {
        const char* qg  = (const char*)(qhi + hb + (size_t)qt * 128 * HD);
        const char* qg2 = (const char*)(qlo + hb + (size_t)qt * 128 * HD);
        #pragma unroll
        for (int it = 0; it < 4; it++) {
            int lin = it * 256 + tid;
            int r = lin >> 3, c = (lin & 7) * 16;
            uint32_t so = swz((uint32_t)(r * 128 + c));
            CP16(sb + so,         qg  + (size_t)r * 128 + c);
            CP16(sb + 16384 + so, qg2 + (size_t)r * 128 + c);
        }
    }
    load_kv(sb + 32768, khi + hb, klo + hb, vhi + hb, 0, tid);
    CP_COMMIT();

    const int nit = 2 * qt + 2;
    float m0 = -INFINITY, m1 = -INFINITY, l0 = 0.f, l1 = 0.f;
    float oacc[8][4];
    #pragma unroll
    for (int jf = 0; jf < 8; jf++)
        #pragma unroll
        for (int e = 0; e < 4; e++) oacc[jf][e] = 0.f;

    const int rowg0 = qt*128 + wid*16 + grp;

    for (int j = 0; j < nit; j++) {
        const uint32_t st = sb + 32768 + (uint32_t)(j & 1) * KV_STAGE;
        CP_WAIT(0);
        __syncthreads();
        if (j + 1 < nit) {
            load_kv(sb + 32768 + (uint32_t)((j + 1) & 1) * KV_STAGE,
                    khi + hb, klo + hb, vhi + hb, (j + 1) * 64, tid);
            CP_COMMIT();
        }

        if (j == 2*qt + 1 && wid < 4) continue;

        float sacc[8][4];
        #pragma unroll
        for (int jf = 0; jf < 8; jf++)
            #pragma unroll
            for (int e = 0; e < 4; e++) sacc[jf][e] = 0.f;

        #pragma unroll
        for (int kk = 0; kk < 4; kk++) {
            const uint32_t kb = (uint32_t)((kk*2 + lchk) * 16);
            const uint32_t ao = swz((uint32_t)((wid*16 + lrow) * 128) + kb);
            uint32_t ah[4], al[4];
            ldsm4(ah, sb + ao);
            ldsm4(al, sb + 16384 + ao);
            #pragma unroll
            for (int jn = 0; jn < 4; jn++) {
                const uint32_t bo = swz((uint32_t)((jn*16 + lrow) * 128) + kb);
                uint32_t bhh[4], bll[4];
                ldsm4(bhh, st + bo);
                ldsm4(bll, st + 8192 + bo);
                mma16816(sacc[2*jn],   ah, bhh[0], bhh[2]);
                mma16816(sacc[2*jn+1], ah, bhh[1], bhh[3]);
                mma16816(sacc[2*jn],   ah, bll[0], bll[2]);
                mma16816(sacc[2*jn+1], ah, bll[1], bll[3]);
                mma16816(sacc[2*jn],   al, bhh[0], bhh[2]);
                mma16816(sacc[2*jn+1], al, bhh[1], bhh[3]);
            }
        }

        if (j >= 2*qt) {
            #pragma unroll
            for (int jf = 0; jf < 8; jf++)
                #pragma unroll
                for (int e = 0; e < 4; e++) {
                    const int colg = j*64 + jf*8 + cb + (e & 1);
                    const int rowg = rowg0 + ((e >= 2) ? 8 : 0);
                    if (colg > rowg) sacc[jf][e] = -1e30f;
                }
        }

        float rmx0 = -3.0e30f, rmx1 = -3.0e30f;
        #pragma unroll
        for (int jf = 0; jf < 8; jf++) {
            rmx0 = fmaxf(rmx0, fmaxf(sacc[jf][0], sacc[jf][1]));
            rmx1 = fmaxf(rmx1, fmaxf(sacc[jf][2], sacc[jf][3]));
        }
        rmx0 = fmaxf(rmx0, __shfl_xor_sync(0xffffffffu, rmx0, 1));
        rmx0 = fmaxf(rmx0, __shfl_xor_sync(0xffffffffu, rmx0, 2));
        rmx1 = fmaxf(rmx1, __shfl_xor_sync(0xffffffffu, rmx1, 1));
        rmx1 = fmaxf(rmx1, __shfl_xor_sync(0xffffffffu, rmx1, 2));
        const float mn0 = fmaxf(m0, rmx0), mn1 = fmaxf(m1, rmx1);
        const float al0 = ex2(m0 - mn0), al1 = ex2(m1 - mn1);
        float rs0 = 0.f, rs1 = 0.f;
        #pragma unroll
        for (int jf = 0; jf < 8; jf++) {
            float p0 = ex2(sacc[jf][0] - mn0); sacc[jf][0] = p0; rs0 += p0;
            float p1 = ex2(sacc[jf][1] - mn0); sacc[jf][1] = p1; rs0 += p1;
            float p2 = ex2(sacc[jf][2] - mn1); sacc[jf][2] = p2; rs1 += p2;
            float p3 = ex2(sacc[jf][3] - mn1); sacc[jf][3] = p3; rs1 += p3;
        }
        l0 = l0*al0 + rs0; m0 = mn0;
        l1 = l1*al1 + rs1; m1 = mn1;
        #pragma unroll
        for (int jf = 0; jf < 8; jf++) {
            oacc[jf][0] *= al0; oacc[jf][1] *= al0;
            oacc[jf][2] *= al1; oacc[jf][3] *= al1;
        }

        // ---- O += P V (fp16 single-pass) ----
        #pragma unroll
        for (int tc = 0; tc < 4; tc++) {
            uint32_t ph[4];
            ph[0] = pack_h(sacc[2*tc][0],   sacc[2*tc][1]);
            ph[1] = pack_h(sacc[2*tc][2],   sacc[2*tc][3]);
            ph[2] = pack_h(sacc[2*tc+1][0], sacc[2*tc+1][1]);
            ph[3] = pack_h(sacc[2*tc+1][2], sacc[2*tc+1][3]);

            #pragma unroll
            for (int dn = 0; dn < 4; dn++) {
                const uint32_t ao = swz((uint32_t)((tc*16 + vrow) * 128 + dn*32 + vcol));
                uint32_t vh4[4];
                ldsm4t(vh4, st + 16384 + ao);
                mma16816h(oacc[2*dn],   ph, vh4[0], vh4[2]);
                mma16816h(oacc[2*dn+1], ph, vh4[1], vh4[3]);
            }
        }
    }

    l0 += __shfl_xor_sync(0xffffffffu, l0, 1);
    l0 += __shfl_xor_sync(0xffffffffu, l0, 2);
    l1 += __shfl_xor_sync(0xffffffffu, l1, 1);
    l1 += __shfl_xor_sync(0xffffffffu, l1, 2);

    const float inv0 = 1.f / l0, inv1 = 1.f / l1;
    #pragma unroll
    for (int jf = 0; jf < 8; jf++)
        #pragma unroll
        for (int e = 0; e < 4; e++) {
            const float o = oacc[jf][e] * ((e >= 2) ? inv1 : inv0);
            const int d  = jf*8 + cb + (e & 1);
            const int sg = qt*128 + wid*16 + grp + ((e >= 2) ? 8 : 0);
            const __nv_bfloat16 hv = __float2bfloat16(o);
            const __nv_bfloat16 lv = __float2bfloat16(o - __bfloat162float(hv));
            const size_t off = ((size_t)b * SEQ + sg) * EMB + h*64 + d;
            ohi[off] = hv; olo[off] = lv;
        }
}

// ---------------------------------------------------------------------------
extern "C" void kernel_launch(void* const* d_in, const int* in_sizes, int n_in,
                              void* d_out, int out_size)
{
    const float* query = (const float*)d_in[0];
    const float* key   = (const float*)d_in[1];
    const float* value = (const float*)d_in[2];
    const float* Wq    = (const float*)d_in[3];
    const float* bq    = (const float*)d_in[4];
    const float* Wk    = (const float*)d_in[5];
    const float* bk    = (const float*)d_in[6];
    const float* Wv    = (const float*)d_in[7];
    const float* bv    = (const float*)d_in[8];
    const float* Wo    = (const float*)d_in[9];
    const float* bo    = (const float*)d_in[10];

    __nv_bfloat16 *qhi, *qlo, *khi, *klo, *vhi, *ahi, *alo;
    cudaGetSymbolAddress((void**)&qhi, g_qhi);
    cudaGetSymbolAddress((void**)&qlo, g_qlo);
    cudaGetSymbolAddress((void**)&khi, g_khi);
    cudaGetSymbolAddress((void**)&klo, g_klo);
    cudaGetSymbolAddress((void**)&vhi, g_vhi);
    cudaGetSymbolAddress((void**)&ahi, g_ahi);
    cudaGetSymbolAddress((void**)&alo, g_alo);

    cudaFuncSetAttribute(tc_gemm_qkv,
                         cudaFuncAttributeMaxDynamicSharedMemorySize, GSM_TOTAL);
    cudaFuncSetAttribute(tc_gemm_o,
                         cudaFuncAttributeMaxDynamicSharedMemorySize, GSM_TOTAL);
    cudaFuncSetAttribute(attn_tc,
                         cudaFuncAttributeMaxDynamicSharedMemorySize, ATT_TOTAL);

    split_all<<<dim3((int)(ANELEM/4)/2048, 1, 8), 256>>>(query, key, value,
                                                         Wq, Wk, Wv, Wo);

    tc_gemm_qkv<<<dim3(EMB/64, MROWS/128, 3), 256, GSM_TOTAL>>>(bq, bk, bv);

    attn_tc<<<dim3(SEQ/128, BS_*NH), 256, ATT_TOTAL>>>(qhi, qlo, khi, klo,
                                                       vhi, ahi, alo);

    tc_gemm_o<<<dim3(EMB/64, MROWS/128), 256, GSM_TOTAL>>>(bo, (float*)d_out);
}